// round 1
// baseline (speedup 1.0000x reference)
#include <cuda_runtime.h>
#include <cstdint>

#define T_TOK 2048
#define HID   2048
#define NEXP  64
#define IDIM  768
#define TOPK  8
#define NPAIR (T_TOK*TOPK)   // 16384

// ---------------- device scratch (static, allocation-free) ----------------
__device__ int   g_topk_idx[NPAIR];
__device__ float g_topk_w[NPAIR];
__device__ int   g_counts[NEXP];
__device__ int   g_offsets[NEXP];
__device__ int   g_list[NEXP*T_TOK];            // pair ids (tok*8+slot), token-ordered per expert
__device__ float g_hbuf[(size_t)NPAIR*IDIM];    // silu(gate)*up rows, grouped by expert
__device__ float g_outbuf[(size_t)NPAIR*HID];   // weighted down-proj rows, indexed by pair id

// ---------------- helpers ----------------
__device__ __forceinline__ float to_tf32(float x) {
    uint32_t u;
    asm("cvt.rna.tf32.f32 %0, %1;" : "=r"(u) : "f"(x));
    return __uint_as_float(u);
}

__device__ __forceinline__ void mma_tf32(float* c, const uint32_t* a, uint32_t b0, uint32_t b1) {
    asm volatile(
        "mma.sync.aligned.m16n8k8.row.col.f32.tf32.tf32.f32 "
        "{%0,%1,%2,%3}, {%4,%5,%6,%7}, {%8,%9}, {%0,%1,%2,%3};\n"
        : "+f"(c[0]), "+f"(c[1]), "+f"(c[2]), "+f"(c[3])
        : "r"(a[0]), "r"(a[1]), "r"(a[2]), "r"(a[3]), "r"(b0), "r"(b1));
}

// ---------------- 1. router: logits + top-8 + renorm weights ----------------
// 128 blocks x 256 threads, 16 tokens/block.
__global__ void router_kernel(const float* __restrict__ x, const float* __restrict__ gw) {
    __shared__ float Xs[16][68];
    __shared__ float Gs[64][68];
    __shared__ float Ls[16][64];
    const int tid = threadIdx.x;
    const int t0  = blockIdx.x * 16;
    const int tl  = tid & 15;        // token within block
    const int eg  = tid >> 4;        // expert group (4 experts each)

    float acc[4] = {0.f, 0.f, 0.f, 0.f};

    for (int kk = 0; kk < HID; kk += 64) {
        // load X tile: 16x64 floats = 256 float4
        {
            int r = tid >> 4, c = (tid & 15) * 4;
            float4 v = *(const float4*)(x + (size_t)(t0 + r) * HID + kk + c);
            Xs[r][c] = v.x; Xs[r][c+1] = v.y; Xs[r][c+2] = v.z; Xs[r][c+3] = v.w;
        }
        // load G tile: 64x64 floats = 1024 float4
        #pragma unroll
        for (int i = 0; i < 4; i++) {
            int idx = i * 256 + tid;
            int r = idx >> 4, c = (idx & 15) * 4;
            float4 v = *(const float4*)(gw + (size_t)r * HID + kk + c);
            Gs[r][c] = v.x; Gs[r][c+1] = v.y; Gs[r][c+2] = v.z; Gs[r][c+3] = v.w;
        }
        __syncthreads();
        #pragma unroll 4
        for (int k = 0; k < 64; k += 4) {
            float4 xv = *(const float4*)&Xs[tl][k];
            #pragma unroll
            for (int j = 0; j < 4; j++) {
                float4 gv = *(const float4*)&Gs[eg*4 + j][k];
                acc[j] += xv.x*gv.x + xv.y*gv.y + xv.z*gv.z + xv.w*gv.w;
            }
        }
        __syncthreads();
    }
    #pragma unroll
    for (int j = 0; j < 4; j++) Ls[tl][eg*4 + j] = acc[j];
    __syncthreads();

    // top-8 per token: warp w handles tokens 2w, 2w+1
    const int wid = tid >> 5, lane = tid & 31;
    for (int j = 0; j < 2; j++) {
        const int tok = wid * 2 + j;
        float v0 = Ls[tok][lane];
        float v1 = Ls[tok][lane + 32];
        bool s0 = false, s1 = false;
        float vals[8]; int idxs[8];
        #pragma unroll
        for (int r = 0; r < 8; r++) {
            float bv = -1e30f; int bi = 1 << 20;
            if (!s0) { bv = v0; bi = lane; }
            if (!s1 && (v1 > bv || (v1 == bv && lane + 32 < bi))) { bv = v1; bi = lane + 32; }
            #pragma unroll
            for (int o = 16; o > 0; o >>= 1) {
                float ov = __shfl_xor_sync(0xffffffffu, bv, o);
                int   oi = __shfl_xor_sync(0xffffffffu, bi, o);
                if (ov > bv || (ov == bv && oi < bi)) { bv = ov; bi = oi; }
            }
            vals[r] = bv; idxs[r] = bi;
            if (bi == lane)      s0 = true;
            if (bi == lane + 32) s1 = true;
        }
        if (lane == 0) {
            float m = vals[0];            // first pick is the max
            float w[8]; float sum = 0.f;
            #pragma unroll
            for (int r = 0; r < 8; r++) { w[r] = __expf(vals[r] - m); sum += w[r]; }
            float inv = 1.f / sum;
            int gt = t0 + tok;
            #pragma unroll
            for (int r = 0; r < 8; r++) {
                g_topk_idx[gt*TOPK + r] = idxs[r];
                g_topk_w  [gt*TOPK + r] = w[r] * inv;
            }
        }
    }
}

// ---------------- 2. deterministic bucketing (one block per expert) -------
__global__ void bucket_kernel() {
    const int e = blockIdx.x;
    const int tid = threadIdx.x;
    __shared__ int warp_tot[8];
    __shared__ int base_s;
    if (tid == 0) base_s = 0;
    __syncthreads();
    const int wid = tid >> 5, lane = tid & 31;
    for (int t0 = 0; t0 < T_TOK; t0 += 256) {
        int t = t0 + tid;
        int slot = -1;
        #pragma unroll
        for (int k = 0; k < TOPK; k++)
            if (g_topk_idx[t*TOPK + k] == e) slot = k;
        unsigned m = __ballot_sync(0xffffffffu, slot >= 0);
        if (lane == 0) warp_tot[wid] = __popc(m);
        __syncthreads();
        int wbase = base_s;
        for (int i = 0; i < wid; i++) wbase += warp_tot[i];
        if (slot >= 0) {
            int pos = wbase + __popc(m & ((1u << lane) - 1u));
            g_list[e*T_TOK + pos] = t*TOPK + slot;
        }
        __syncthreads();
        if (tid == 0) {
            int tot = 0;
            for (int i = 0; i < 8; i++) tot += warp_tot[i];
            base_s += tot;
        }
        __syncthreads();
    }
    if (tid == 0) g_counts[e] = base_s;
}

__global__ void offsets_kernel() {
    if (threadIdx.x == 0 && blockIdx.x == 0) {
        int s = 0;
        for (int e = 0; e < NEXP; e++) { g_offsets[e] = s; s += g_counts[e]; }
    }
}

// ---------------- 3. GEMM1: h = silu(X Wg^T) * (X Wu^T) --------------------
// BM=128, BN=64 (per matrix, gate+up fused), BK=32. 4 warps, warp tile 32x64.
__global__ void __launch_bounds__(128, 2)
gemm_gateup(const float* __restrict__ hidden,
            const float* __restrict__ wg,
            const float* __restrict__ wu) {
    const int mb = blockIdx.x, nb = blockIdx.y, e = blockIdx.z;
    const int cnt = g_counts[e];
    if (mb * 128 >= cnt) return;
    const int base = g_offsets[e];

    __shared__ float As [128][36];
    __shared__ float Bgs[64][36];
    __shared__ float Bus[64][36];
    __shared__ int   toks_s[128];

    const int tid = threadIdx.x;
    {
        int m = mb * 128 + tid;
        toks_s[tid] = (m < cnt) ? (g_list[e*T_TOK + m] >> 3) : -1;
    }
    __syncthreads();

    const int n0 = nb * 64;
    const float* wg_p = wg + ((size_t)e * IDIM + n0) * HID;
    const float* wu_p = wu + ((size_t)e * IDIM + n0) * HID;

    float cg[2][8][4];
    float cu[2][8][4];
    #pragma unroll
    for (int a = 0; a < 2; a++)
        #pragma unroll
        for (int b = 0; b < 8; b++)
            #pragma unroll
            for (int c = 0; c < 4; c++) { cg[a][b][c] = 0.f; cu[a][b][c] = 0.f; }

    const int wid = tid >> 5, lane = tid & 31;
    const int grp = lane >> 2, tg = lane & 3;

    for (int kk = 0; kk < HID; kk += 32) {
        // ---- loads ----
        #pragma unroll
        for (int i = 0; i < 8; i++) {
            int idx = i * 128 + tid;
            int r = idx >> 3, c = (idx & 7) * 4;
            int tok = toks_s[r];
            float4 v = make_float4(0.f, 0.f, 0.f, 0.f);
            if (tok >= 0) v = *(const float4*)(hidden + (size_t)tok * HID + kk + c);
            As[r][c]   = to_tf32(v.x); As[r][c+1] = to_tf32(v.y);
            As[r][c+2] = to_tf32(v.z); As[r][c+3] = to_tf32(v.w);
        }
        #pragma unroll
        for (int i = 0; i < 4; i++) {
            int idx = i * 128 + tid;
            int r = idx >> 3, c = (idx & 7) * 4;
            float4 gv = *(const float4*)(wg_p + (size_t)r * HID + kk + c);
            Bgs[r][c]   = to_tf32(gv.x); Bgs[r][c+1] = to_tf32(gv.y);
            Bgs[r][c+2] = to_tf32(gv.z); Bgs[r][c+3] = to_tf32(gv.w);
            float4 uv = *(const float4*)(wu_p + (size_t)r * HID + kk + c);
            Bus[r][c]   = to_tf32(uv.x); Bus[r][c+1] = to_tf32(uv.y);
            Bus[r][c+2] = to_tf32(uv.z); Bus[r][c+3] = to_tf32(uv.w);
        }
        __syncthreads();
        // ---- compute ----
        #pragma unroll
        for (int ks = 0; ks < 4; ks++) {
            const int kc = ks * 8 + tg;
            uint32_t a[2][4];
            #pragma unroll
            for (int mt = 0; mt < 2; mt++) {
                int r0 = wid * 32 + mt * 16 + grp;
                a[mt][0] = __float_as_uint(As[r0    ][kc]);
                a[mt][1] = __float_as_uint(As[r0 + 8][kc]);
                a[mt][2] = __float_as_uint(As[r0    ][kc + 4]);
                a[mt][3] = __float_as_uint(As[r0 + 8][kc + 4]);
            }
            #pragma unroll
            for (int nt = 0; nt < 8; nt++) {
                int rn = nt * 8 + grp;
                uint32_t bg0 = __float_as_uint(Bgs[rn][kc]);
                uint32_t bg1 = __float_as_uint(Bgs[rn][kc + 4]);
                uint32_t bu0 = __float_as_uint(Bus[rn][kc]);
                uint32_t bu1 = __float_as_uint(Bus[rn][kc + 4]);
                mma_tf32(cg[0][nt], a[0], bg0, bg1);
                mma_tf32(cg[1][nt], a[1], bg0, bg1);
                mma_tf32(cu[0][nt], a[0], bu0, bu1);
                mma_tf32(cu[1][nt], a[1], bu0, bu1);
            }
        }
        __syncthreads();
    }

    // ---- epilogue: silu(g)*u -> g_hbuf ----
    #pragma unroll
    for (int mt = 0; mt < 2; mt++) {
        #pragma unroll
        for (int half = 0; half < 2; half++) {
            int row = wid * 32 + mt * 16 + grp + half * 8;
            int m = mb * 128 + row;
            if (m < cnt) {
                float* hrow = g_hbuf + (size_t)(base + m) * IDIM + n0;
                #pragma unroll
                for (int nt = 0; nt < 8; nt++) {
                    int col = nt * 8 + tg * 2;
                    float g0 = cg[mt][nt][half*2 + 0], u0 = cu[mt][nt][half*2 + 0];
                    float g1 = cg[mt][nt][half*2 + 1], u1 = cu[mt][nt][half*2 + 1];
                    float2 hv;
                    hv.x = g0 * u0 / (1.f + __expf(-g0));
                    hv.y = g1 * u1 / (1.f + __expf(-g1));
                    *(float2*)(hrow + col) = hv;
                }
            }
        }
    }
}

// ---------------- 4. GEMM2: y = (h Wd^T) * combine_w -> g_outbuf ----------
// BM=128, BN=128, BK=32. 4 warps, warp tile 32x128 (16 n-tiles).
__global__ void __launch_bounds__(128, 2)
gemm_down(const float* __restrict__ wd) {
    const int mb = blockIdx.x, nb = blockIdx.y, e = blockIdx.z;
    const int cnt = g_counts[e];
    if (mb * 128 >= cnt) return;
    const int base = g_offsets[e];

    __shared__ float As [128][36];
    __shared__ float Bds[128][36];
    __shared__ int   pairs_s[128];

    const int tid = threadIdx.x;
    {
        int m = mb * 128 + tid;
        pairs_s[tid] = (m < cnt) ? g_list[e*T_TOK + m] : -1;
    }
    __syncthreads();

    const int n0 = nb * 128;
    const float* wd_p = wd + ((size_t)e * HID + n0) * IDIM;
    const float* arow0 = g_hbuf + (size_t)(base + mb * 128) * IDIM;

    float cd[2][16][4];
    #pragma unroll
    for (int a = 0; a < 2; a++)
        #pragma unroll
        for (int b = 0; b < 16; b++)
            #pragma unroll
            for (int c = 0; c < 4; c++) cd[a][b][c] = 0.f;

    const int wid = tid >> 5, lane = tid & 31;
    const int grp = lane >> 2, tg = lane & 3;

    for (int kk = 0; kk < IDIM; kk += 32) {
        #pragma unroll
        for (int i = 0; i < 8; i++) {
            int idx = i * 128 + tid;
            int r = idx >> 3, c = (idx & 7) * 4;
            float4 v = make_float4(0.f, 0.f, 0.f, 0.f);
            if (pairs_s[r] >= 0) v = *(const float4*)(arow0 + (size_t)r * IDIM + kk + c);
            As[r][c]   = to_tf32(v.x); As[r][c+1] = to_tf32(v.y);
            As[r][c+2] = to_tf32(v.z); As[r][c+3] = to_tf32(v.w);
        }
        #pragma unroll
        for (int i = 0; i < 8; i++) {
            int idx = i * 128 + tid;
            int r = idx >> 3, c = (idx & 7) * 4;
            float4 v = *(const float4*)(wd_p + (size_t)r * IDIM + kk + c);
            Bds[r][c]   = to_tf32(v.x); Bds[r][c+1] = to_tf32(v.y);
            Bds[r][c+2] = to_tf32(v.z); Bds[r][c+3] = to_tf32(v.w);
        }
        __syncthreads();
        #pragma unroll
        for (int ks = 0; ks < 4; ks++) {
            const int kc = ks * 8 + tg;
            uint32_t a[2][4];
            #pragma unroll
            for (int mt = 0; mt < 2; mt++) {
                int r0 = wid * 32 + mt * 16 + grp;
                a[mt][0] = __float_as_uint(As[r0    ][kc]);
                a[mt][1] = __float_as_uint(As[r0 + 8][kc]);
                a[mt][2] = __float_as_uint(As[r0    ][kc + 4]);
                a[mt][3] = __float_as_uint(As[r0 + 8][kc + 4]);
            }
            #pragma unroll
            for (int nt = 0; nt < 16; nt++) {
                int rn = nt * 8 + grp;
                uint32_t b0 = __float_as_uint(Bds[rn][kc]);
                uint32_t b1 = __float_as_uint(Bds[rn][kc + 4]);
                mma_tf32(cd[0][nt], a[0], b0, b1);
                mma_tf32(cd[1][nt], a[1], b0, b1);
            }
        }
        __syncthreads();
    }

    // ---- epilogue: scale by combine weight, write per-pair row ----
    #pragma unroll
    for (int mt = 0; mt < 2; mt++) {
        #pragma unroll
        for (int half = 0; half < 2; half++) {
            int row = wid * 32 + mt * 16 + grp + half * 8;
            int pair = pairs_s[row];
            if (pair >= 0) {
                float w = g_topk_w[pair];
                float* orow = g_outbuf + (size_t)pair * HID + n0;
                #pragma unroll
                for (int nt = 0; nt < 16; nt++) {
                    int col = nt * 8 + tg * 2;
                    float2 ov;
                    ov.x = cd[mt][nt][half*2 + 0] * w;
                    ov.y = cd[mt][nt][half*2 + 1] * w;
                    *(float2*)(orow + col) = ov;
                }
            }
        }
    }
}

// ---------------- 5. deterministic final reduce over 8 slots --------------
__global__ void reduce_kernel(float* __restrict__ out) {
    int idx = blockIdx.x * blockDim.x + threadIdx.x;   // over T*H/4 float4s
    int t = idx >> 9;            // HID/4 = 512 float4 per row
    int h4 = idx & 511;
    const float4* ob = (const float4*)g_outbuf;
    float4 s = ob[(size_t)(t * TOPK) * (HID/4) + h4];
    #pragma unroll
    for (int k = 1; k < TOPK; k++) {
        float4 v = ob[(size_t)(t * TOPK + k) * (HID/4) + h4];
        s.x += v.x; s.y += v.y; s.z += v.z; s.w += v.w;
    }
    ((float4*)out)[idx] = s;
}

// ---------------- launch ----------------
extern "C" void kernel_launch(void* const* d_in, const int* in_sizes, int n_in,
                              void* d_out, int out_size) {
    (void)in_sizes; (void)n_in; (void)out_size;
    const float* hidden = (const float*)d_in[0];
    const float* gate_w = (const float*)d_in[1];
    const float* w_gate = (const float*)d_in[2];
    const float* w_up   = (const float*)d_in[3];
    const float* w_down = (const float*)d_in[4];
    float* out = (float*)d_out;

    router_kernel<<<T_TOK/16, 256>>>(hidden, gate_w);
    bucket_kernel<<<NEXP, 256>>>();
    offsets_kernel<<<1, 32>>>();
    // grid: mb fastest, expert outermost -> expert weights stay L2-resident
    gemm_gateup<<<dim3(T_TOK/128, IDIM/64, NEXP), 128>>>(hidden, w_gate, w_up);
    gemm_down  <<<dim3(T_TOK/128, HID/128, NEXP), 128>>>(w_down);
    reduce_kernel<<<(T_TOK*(HID/4))/256, 256>>>(out);
}

// round 2
// speedup vs baseline: 2.1616x; 2.1616x over previous
#include <cuda_runtime.h>
#include <cstdint>

#define T_TOK 2048
#define HID   2048
#define NEXP  64
#define IDIM  768
#define TOPK  8
#define NPAIR (T_TOK*TOPK)   // 16384

#define PITCH 36
#define STAGE (256*PITCH)          // floats per pipeline stage (A 128 rows + B 128 rows)
#define SMEM_BYTES (3*STAGE*4)     // 110592 B

// ---------------- device scratch (static, allocation-free) ----------------
__device__ int   g_topk_idx[NPAIR];
__device__ float g_topk_w[NPAIR];
__device__ int   g_counts[NEXP];
__device__ int   g_offsets[NEXP];
__device__ int   g_list[NEXP*T_TOK];                   // pair ids, token-ordered per expert
__device__ float g_hbuf[(size_t)(NPAIR+128)*IDIM];     // silu(gate)*up rows (expert-grouped)
__device__ float g_outbuf[(size_t)NPAIR*HID];          // weighted down rows by pair id

// ---------------- helpers ----------------
__device__ __forceinline__ uint32_t lds_tf32(const float* p) {
    float v = *p;
    uint32_t u; asm("cvt.rna.tf32.f32 %0, %1;" : "=r"(u) : "f"(v));
    return u;
}

__device__ __forceinline__ void mma_tf32(float* c, const uint32_t* a, uint32_t b0, uint32_t b1) {
    asm volatile(
        "mma.sync.aligned.m16n8k8.row.col.f32.tf32.tf32.f32 "
        "{%0,%1,%2,%3}, {%4,%5,%6,%7}, {%8,%9}, {%0,%1,%2,%3};\n"
        : "+f"(c[0]), "+f"(c[1]), "+f"(c[2]), "+f"(c[3])
        : "r"(a[0]), "r"(a[1]), "r"(a[2]), "r"(a[3]), "r"(b0), "r"(b1));
}

__device__ __forceinline__ void cp_async16(uint32_t smem_addr, const void* gptr, int src_bytes) {
    asm volatile("cp.async.cg.shared.global [%0], [%1], 16, %2;\n"
                 :: "r"(smem_addr), "l"(gptr), "r"(src_bytes));
}
__device__ __forceinline__ void cp_commit() { asm volatile("cp.async.commit_group;\n"); }
template<int N> __device__ __forceinline__ void cp_wait() {
    asm volatile("cp.async.wait_group %0;\n" :: "n"(N));
}

// ---------------- 1. router: logits + top-8 + renorm weights ----------------
__global__ void router_kernel(const float* __restrict__ x, const float* __restrict__ gw) {
    __shared__ float Xs[16][68];
    __shared__ float Gs[64][68];
    __shared__ float Ls[16][64];
    const int tid = threadIdx.x;
    const int t0  = blockIdx.x * 16;
    const int tl  = tid & 15;
    const int eg  = tid >> 4;

    float acc[4] = {0.f, 0.f, 0.f, 0.f};

    for (int kk = 0; kk < HID; kk += 64) {
        {
            int r = tid >> 4, c = (tid & 15) * 4;
            float4 v = *(const float4*)(x + (size_t)(t0 + r) * HID + kk + c);
            Xs[r][c] = v.x; Xs[r][c+1] = v.y; Xs[r][c+2] = v.z; Xs[r][c+3] = v.w;
        }
        #pragma unroll
        for (int i = 0; i < 4; i++) {
            int idx = i * 256 + tid;
            int r = idx >> 4, c = (idx & 15) * 4;
            float4 v = *(const float4*)(gw + (size_t)r * HID + kk + c);
            Gs[r][c] = v.x; Gs[r][c+1] = v.y; Gs[r][c+2] = v.z; Gs[r][c+3] = v.w;
        }
        __syncthreads();
        #pragma unroll 4
        for (int k = 0; k < 64; k += 4) {
            float4 xv = *(const float4*)&Xs[tl][k];
            #pragma unroll
            for (int j = 0; j < 4; j++) {
                float4 gv = *(const float4*)&Gs[eg*4 + j][k];
                acc[j] += xv.x*gv.x + xv.y*gv.y + xv.z*gv.z + xv.w*gv.w;
            }
        }
        __syncthreads();
    }
    #pragma unroll
    for (int j = 0; j < 4; j++) Ls[tl][eg*4 + j] = acc[j];
    __syncthreads();

    const int wid = tid >> 5, lane = tid & 31;
    for (int j = 0; j < 2; j++) {
        const int tok = wid * 2 + j;
        float v0 = Ls[tok][lane];
        float v1 = Ls[tok][lane + 32];
        bool s0 = false, s1 = false;
        float vals[8]; int idxs[8];
        #pragma unroll
        for (int r = 0; r < 8; r++) {
            float bv = -1e30f; int bi = 1 << 20;
            if (!s0) { bv = v0; bi = lane; }
            if (!s1 && (v1 > bv || (v1 == bv && lane + 32 < bi))) { bv = v1; bi = lane + 32; }
            #pragma unroll
            for (int o = 16; o > 0; o >>= 1) {
                float ov = __shfl_xor_sync(0xffffffffu, bv, o);
                int   oi = __shfl_xor_sync(0xffffffffu, bi, o);
                if (ov > bv || (ov == bv && oi < bi)) { bv = ov; bi = oi; }
            }
            vals[r] = bv; idxs[r] = bi;
            if (bi == lane)      s0 = true;
            if (bi == lane + 32) s1 = true;
        }
        if (lane == 0) {
            float m = vals[0];
            float w[8]; float sum = 0.f;
            #pragma unroll
            for (int r = 0; r < 8; r++) { w[r] = __expf(vals[r] - m); sum += w[r]; }
            float inv = 1.f / sum;
            int gt = t0 + tok;
            #pragma unroll
            for (int r = 0; r < 8; r++) {
                g_topk_idx[gt*TOPK + r] = idxs[r];
                g_topk_w  [gt*TOPK + r] = w[r] * inv;
            }
        }
    }
}

// ---------------- 2. deterministic bucketing (one block per expert) -------
__global__ void bucket_kernel() {
    const int e = blockIdx.x;
    const int tid = threadIdx.x;
    __shared__ int warp_tot[8];
    __shared__ int base_s;
    if (tid == 0) base_s = 0;
    __syncthreads();
    const int wid = tid >> 5, lane = tid & 31;
    for (int t0 = 0; t0 < T_TOK; t0 += 256) {
        int t = t0 + tid;
        int slot = -1;
        #pragma unroll
        for (int k = 0; k < TOPK; k++)
            if (g_topk_idx[t*TOPK + k] == e) slot = k;
        unsigned m = __ballot_sync(0xffffffffu, slot >= 0);
        if (lane == 0) warp_tot[wid] = __popc(m);
        __syncthreads();
        int wbase = base_s;
        for (int i = 0; i < wid; i++) wbase += warp_tot[i];
        if (slot >= 0) {
            int pos = wbase + __popc(m & ((1u << lane) - 1u));
            g_list[e*T_TOK + pos] = t*TOPK + slot;
        }
        __syncthreads();
        if (tid == 0) {
            int tot = 0;
            for (int i = 0; i < 8; i++) tot += warp_tot[i];
            base_s += tot;
        }
        __syncthreads();
    }
    if (tid == 0) g_counts[e] = base_s;
}

__global__ void offsets_kernel() {
    if (threadIdx.x == 0 && blockIdx.x == 0) {
        int s = 0;
        for (int e = 0; e < NEXP; e++) { g_offsets[e] = s; s += g_counts[e]; }
    }
}

// ---------------- 3. GEMM1: h = silu(X Wg^T) * (X Wu^T) --------------------
// 256 threads, BM=128, BN=64(gate)+64(up), BK=32, 3-stage cp.async pipeline.
// Warp grid 4(m) x 2(n); warp tile 32 x (32 gate + 32 up).
__global__ void __launch_bounds__(256, 2)
gemm_gateup(const float* __restrict__ hidden,
            const float* __restrict__ wg,
            const float* __restrict__ wu) {
    const int mb = blockIdx.x, nb = blockIdx.y, e = blockIdx.z;
    const int cnt = g_counts[e];
    if (mb * 128 >= cnt) return;
    const int base = g_offsets[e];

    extern __shared__ float smem[];
    __shared__ int toks_s[128];

    const int tid = threadIdx.x;
    if (tid < 128) {
        int m = mb * 128 + tid;
        toks_s[tid] = (m < cnt) ? (g_list[e*T_TOK + m] >> 3) : -1;
    }
    __syncthreads();

    const int n0 = nb * 64;
    const float* wg_p = wg + ((size_t)e * IDIM + n0) * HID;
    const float* wu_p = wu + ((size_t)e * IDIM + n0) * HID;

    const uint32_t smem_u = (uint32_t)__cvta_generic_to_shared(smem);

    // ---- pipeline load: stage s <- k-tile kt ----
    auto load_stage = [&](int kt, int s) {
        const int kk = kt * 32;
        const uint32_t stA = smem_u + (uint32_t)(s * STAGE) * 4u;
        const uint32_t stB = stA + 128u * PITCH * 4u;
        #pragma unroll
        for (int i = 0; i < 4; i++) {
            int idx = i * 256 + tid;
            int r = idx >> 3, c = (idx & 7) * 4;
            int tok = toks_s[r];
            const float* src = (tok >= 0) ? hidden + (size_t)tok * HID + kk + c : hidden;
            cp_async16(stA + (uint32_t)(r * PITCH + c) * 4u, src, (tok >= 0) ? 16 : 0);
        }
        #pragma unroll
        for (int i = 0; i < 4; i++) {
            int idx = i * 256 + tid;
            int r = idx >> 3, c = (idx & 7) * 4;
            const float* src = (r < 64) ? wg_p + (size_t)r * HID + kk + c
                                        : wu_p + (size_t)(r - 64) * HID + kk + c;
            cp_async16(stB + (uint32_t)(r * PITCH + c) * 4u, src, 16);
        }
    };

    float cg[2][4][4], cu[2][4][4];
    #pragma unroll
    for (int a = 0; a < 2; a++)
        #pragma unroll
        for (int b = 0; b < 4; b++)
            #pragma unroll
            for (int c = 0; c < 4; c++) { cg[a][b][c] = 0.f; cu[a][b][c] = 0.f; }

    const int wid = tid >> 5, lane = tid & 31;
    const int wm = wid & 3, wn = wid >> 2;        // 4 x 2 warp grid
    const int grp = lane >> 2, tg = lane & 3;

    const int KT = HID / 32;                       // 64
    load_stage(0, 0); cp_commit();
    load_stage(1, 1); cp_commit();

    for (int kt = 0; kt < KT; kt++) {
        cp_wait<1>();
        __syncthreads();
        if (kt + 2 < KT) load_stage(kt + 2, (kt + 2) % 3);
        cp_commit();

        const float* stA = smem + (kt % 3) * STAGE;
        const float* stB = stA + 128 * PITCH;
        #pragma unroll
        for (int ks = 0; ks < 4; ks++) {
            const int kc = ks * 8 + tg;
            uint32_t a[2][4];
            #pragma unroll
            for (int mt = 0; mt < 2; mt++) {
                int r0 = wm * 32 + mt * 16 + grp;
                a[mt][0] = lds_tf32(&stA[ r0      * PITCH + kc]);
                a[mt][1] = lds_tf32(&stA[(r0 + 8) * PITCH + kc]);
                a[mt][2] = lds_tf32(&stA[ r0      * PITCH + kc + 4]);
                a[mt][3] = lds_tf32(&stA[(r0 + 8) * PITCH + kc + 4]);
            }
            #pragma unroll
            for (int nt = 0; nt < 4; nt++) {
                int rn = wn * 32 + nt * 8 + grp;
                uint32_t bg0 = lds_tf32(&stB[ rn       * PITCH + kc]);
                uint32_t bg1 = lds_tf32(&stB[ rn       * PITCH + kc + 4]);
                uint32_t bu0 = lds_tf32(&stB[(rn + 64) * PITCH + kc]);
                uint32_t bu1 = lds_tf32(&stB[(rn + 64) * PITCH + kc + 4]);
                mma_tf32(cg[0][nt], a[0], bg0, bg1);
                mma_tf32(cg[1][nt], a[1], bg0, bg1);
                mma_tf32(cu[0][nt], a[0], bu0, bu1);
                mma_tf32(cu[1][nt], a[1], bu0, bu1);
            }
        }
    }

    // ---- epilogue: silu(g)*u -> g_hbuf ----
    #pragma unroll
    for (int mt = 0; mt < 2; mt++) {
        #pragma unroll
        for (int half = 0; half < 2; half++) {
            int row = wm * 32 + mt * 16 + half * 8 + grp;
            int m = mb * 128 + row;
            if (m < cnt) {
                float* hrow = g_hbuf + (size_t)(base + m) * IDIM + n0;
                #pragma unroll
                for (int nt = 0; nt < 4; nt++) {
                    int col = wn * 32 + nt * 8 + tg * 2;
                    float g0 = cg[mt][nt][half*2 + 0], u0 = cu[mt][nt][half*2 + 0];
                    float g1 = cg[mt][nt][half*2 + 1], u1 = cu[mt][nt][half*2 + 1];
                    float2 hv;
                    hv.x = g0 * u0 / (1.f + __expf(-g0));
                    hv.y = g1 * u1 / (1.f + __expf(-g1));
                    *(float2*)(hrow + col) = hv;
                }
            }
        }
    }
}

// ---------------- 4. GEMM2: y = (h Wd^T) * combine_w -> g_outbuf ----------
// 256 threads, BM=128, BN=128, BK=32, 3-stage cp.async pipeline.
// Warp grid 4(m) x 2(n); warp tile 32 x 64.
__global__ void __launch_bounds__(256, 2)
gemm_down(const float* __restrict__ wd) {
    const int mb = blockIdx.x, nb = blockIdx.y, e = blockIdx.z;
    const int cnt = g_counts[e];
    if (mb * 128 >= cnt) return;
    const int base = g_offsets[e];

    extern __shared__ float smem[];
    __shared__ int pairs_s[128];

    const int tid = threadIdx.x;
    if (tid < 128) {
        int m = mb * 128 + tid;
        pairs_s[tid] = (m < cnt) ? g_list[e*T_TOK + m] : -1;
    }
    __syncthreads();

    const int n0 = nb * 128;
    const float* wd_p  = wd + ((size_t)e * HID + n0) * IDIM;
    const float* arow0 = g_hbuf + (size_t)(base + mb * 128) * IDIM;

    const uint32_t smem_u = (uint32_t)__cvta_generic_to_shared(smem);

    auto load_stage = [&](int kt, int s) {
        const int kk = kt * 32;
        const uint32_t stA = smem_u + (uint32_t)(s * STAGE) * 4u;
        const uint32_t stB = stA + 128u * PITCH * 4u;
        #pragma unroll
        for (int i = 0; i < 4; i++) {
            int idx = i * 256 + tid;
            int r = idx >> 3, c = (idx & 7) * 4;
            bool val = pairs_s[r] >= 0;
            const float* src = val ? arow0 + (size_t)r * IDIM + kk + c : g_hbuf;
            cp_async16(stA + (uint32_t)(r * PITCH + c) * 4u, src, val ? 16 : 0);
        }
        #pragma unroll
        for (int i = 0; i < 4; i++) {
            int idx = i * 256 + tid;
            int r = idx >> 3, c = (idx & 7) * 4;
            cp_async16(stB + (uint32_t)(r * PITCH + c) * 4u,
                       wd_p + (size_t)r * IDIM + kk + c, 16);
        }
    };

    float cd[2][8][4];
    #pragma unroll
    for (int a = 0; a < 2; a++)
        #pragma unroll
        for (int b = 0; b < 8; b++)
            #pragma unroll
            for (int c = 0; c < 4; c++) cd[a][b][c] = 0.f;

    const int wid = tid >> 5, lane = tid & 31;
    const int wm = wid & 3, wn = wid >> 2;
    const int grp = lane >> 2, tg = lane & 3;

    const int KT = IDIM / 32;                      // 24
    load_stage(0, 0); cp_commit();
    load_stage(1, 1); cp_commit();

    for (int kt = 0; kt < KT; kt++) {
        cp_wait<1>();
        __syncthreads();
        if (kt + 2 < KT) load_stage(kt + 2, (kt + 2) % 3);
        cp_commit();

        const float* stA = smem + (kt % 3) * STAGE;
        const float* stB = stA + 128 * PITCH;
        #pragma unroll
        for (int ks = 0; ks < 4; ks++) {
            const int kc = ks * 8 + tg;
            uint32_t a[2][4];
            #pragma unroll
            for (int mt = 0; mt < 2; mt++) {
                int r0 = wm * 32 + mt * 16 + grp;
                a[mt][0] = lds_tf32(&stA[ r0      * PITCH + kc]);
                a[mt][1] = lds_tf32(&stA[(r0 + 8) * PITCH + kc]);
                a[mt][2] = lds_tf32(&stA[ r0      * PITCH + kc + 4]);
                a[mt][3] = lds_tf32(&stA[(r0 + 8) * PITCH + kc + 4]);
            }
            #pragma unroll
            for (int nt = 0; nt < 8; nt++) {
                int rn = wn * 64 + nt * 8 + grp;
                uint32_t b0 = lds_tf32(&stB[rn * PITCH + kc]);
                uint32_t b1 = lds_tf32(&stB[rn * PITCH + kc + 4]);
                mma_tf32(cd[0][nt], a[0], b0, b1);
                mma_tf32(cd[1][nt], a[1], b0, b1);
            }
        }
    }

    // ---- epilogue: scale by combine weight, write per-pair row ----
    #pragma unroll
    for (int mt = 0; mt < 2; mt++) {
        #pragma unroll
        for (int half = 0; half < 2; half++) {
            int row = wm * 32 + mt * 16 + half * 8 + grp;
            int pair = pairs_s[row];
            if (pair >= 0) {
                float w = g_topk_w[pair];
                float* orow = g_outbuf + (size_t)pair * HID + n0;
                #pragma unroll
                for (int nt = 0; nt < 8; nt++) {
                    int col = wn * 64 + nt * 8 + tg * 2;
                    float2 ov;
                    ov.x = cd[mt][nt][half*2 + 0] * w;
                    ov.y = cd[mt][nt][half*2 + 1] * w;
                    *(float2*)(orow + col) = ov;
                }
            }
        }
    }
}

// ---------------- 5. deterministic final reduce over 8 slots --------------
__global__ void reduce_kernel(float* __restrict__ out) {
    int idx = blockIdx.x * blockDim.x + threadIdx.x;
    int t = idx >> 9;
    int h4 = idx & 511;
    const float4* ob = (const float4*)g_outbuf;
    float4 s = ob[(size_t)(t * TOPK) * (HID/4) + h4];
    #pragma unroll
    for (int k = 1; k < TOPK; k++) {
        float4 v = ob[(size_t)(t * TOPK + k) * (HID/4) + h4];
        s.x += v.x; s.y += v.y; s.z += v.z; s.w += v.w;
    }
    ((float4*)out)[idx] = s;
}

// ---------------- launch ----------------
extern "C" void kernel_launch(void* const* d_in, const int* in_sizes, int n_in,
                              void* d_out, int out_size) {
    (void)in_sizes; (void)n_in; (void)out_size;
    const float* hidden = (const float*)d_in[0];
    const float* gate_w = (const float*)d_in[1];
    const float* w_gate = (const float*)d_in[2];
    const float* w_up   = (const float*)d_in[3];
    const float* w_down = (const float*)d_in[4];
    float* out = (float*)d_out;

    cudaFuncSetAttribute(gemm_gateup, cudaFuncAttributeMaxDynamicSharedMemorySize, SMEM_BYTES);
    cudaFuncSetAttribute(gemm_down,   cudaFuncAttributeMaxDynamicSharedMemorySize, SMEM_BYTES);

    router_kernel<<<T_TOK/16, 256>>>(hidden, gate_w);
    bucket_kernel<<<NEXP, 256>>>();
    offsets_kernel<<<1, 32>>>();
    gemm_gateup<<<dim3(T_TOK/128, IDIM/64, NEXP), 256, SMEM_BYTES>>>(hidden, w_gate, w_up);
    gemm_down  <<<dim3(T_TOK/128, HID/128, NEXP), 256, SMEM_BYTES>>>(w_down);
    reduce_kernel<<<(T_TOK*(HID/4))/256, 256>>>(out);
}